// round 15
// baseline (speedup 1.0000x reference)
#include <cuda_runtime.h>

#define NPTS   4096
#define NPROB  4
#define NW     128             // 4096 cells / 32
#define EMAXG  (1 << 17)       // global edge capacity per problem
#define SEC    16384           // K3 shared edge stage capacity
#define BEC    2048            // K2 per-block shared edge buffer
#define POSB   (NPTS * 16)     // 64 KB position stage

static __device__ float4   g_pos[NPROB][NPTS];    // .x=z .y=y .z=x .w=aa
static __device__ unsigned g_prio[NPROB][NPTS];   // priority bits (asc = higher)
static __device__ unsigned g_vmask[NPROB][NW];    // valid-cell bitset
static __device__ unsigned g_alive[NPROB][NW];    // post-NMS alive bitset
static __device__ unsigned g_edges[NPROB][EMAXG]; // (succ<<12)|pred (cell ids)
static __device__ int      g_ecnt[NPROB];
static __device__ int      g_cnt[NPROB][3];       // tp, lp, lt

// XLA logistic(x) = 0.5 + 0.5*tanh(0.5x), Eigen rational tanh (bit-matched)
__device__ __forceinline__ float xla_logistic(float x) {
    float t  = 0.5f * x;
    float ax = fabsf(t);
    float xc = fminf(fmaxf(t, -7.90531110763549805f), 7.90531110763549805f);
    float x2 = xc * xc;
    float p = fmaf(x2, -2.76076847742355e-16f, 2.00018790482477e-13f);
    p = fmaf(x2, p, -8.60467152213735e-11f);
    p = fmaf(x2, p,  5.12229709037114e-08f);
    p = fmaf(x2, p,  1.48572235717979e-05f);
    p = fmaf(x2, p,  6.37261928875436e-04f);
    p = fmaf(x2, p,  4.89352455891786e-03f);
    p = xc * p;
    float q = fmaf(x2, 1.19825839466702e-06f, 1.18534705686654e-04f);
    q = fmaf(x2, q, 2.26843463243900e-03f);
    q = fmaf(x2, q, 4.89352518554385e-03f);
    float y = p / q;
    if (ax < 0.0004f) y = t;
    return __fadd_rn(__fmul_rn(0.5f, y), 0.5f);
}

// 5x5x5 stencil minus offsets with >=2 coords of |2| (min dist^2 there
// > 1.125 > cutoff^2).  half=1: lexicographically-positive offsets only
// (center excluded by lex filter).  half=0: full stencil INCLUDING center.
__device__ __forceinline__ void build_stencil(int tid, int half,
                                              int* tab, int* cnt)
{
    if (tid < 125) {
        int dz = tid / 25 - 2;
        int r  = tid % 25;
        int dy = r / 5 - 2;
        int dx = r % 5 - 2;
        int n2c = (dz == 2 || dz == -2) + (dy == 2 || dy == -2) +
                  (dx == 2 || dx == -2);
        bool keep = (n2c < 2);
        if (half)
            keep = keep && ((dz > 0) || (dz == 0 && (dy > 0 || (dy == 0 && dx > 0))));
        if (keep) {
            int s = atomicAdd(cnt, 1);
            tab[s] = (dz + 2) | ((dy + 2) << 3) | ((dx + 2) << 6);
        }
    }
}

// ---------------------------------------------------------------------------
// K1: per-cell conf/argmax, positions (+aa), priority, validity bitset.
// grid (16, NPROB) x 256 — one thread per cell.
// ---------------------------------------------------------------------------
__global__ __launch_bounds__(256) void k_prep(
    const float* __restrict__ pred_clses,
    const float* __restrict__ pred_boxes)
{
    int prob = blockIdx.y;
    int b    = prob >> 1;
    int cls  = (prob & 1) + 1;
    int tid  = threadIdx.x;
    int n    = blockIdx.x * 256 + tid;

    if (blockIdx.x == 0) {
        if (tid == 0) g_ecnt[prob] = 0;
        if (tid < 3)  g_cnt[prob][tid] = 0;
    }

    float cv0 = pred_clses[(b * 3 + 0) * NPTS + n];
    float cv1 = pred_clses[(b * 3 + 1) * NPTS + n];
    float cv2 = pred_clses[(b * 3 + 2) * NPTS + n];
    float conf = cv0; int arg = 0;
    if (cv1 > conf) { conf = cv1; arg = 1; }
    if (cv2 > conf) { conf = cv2; arg = 2; }
    bool valid = (arg == cls);

    unsigned bal = __ballot_sync(0xFFFFFFFFu, valid);
    if ((tid & 31) == 0) g_vmask[prob][n >> 5] = bal;

    if (valid) {
        int d = n >> 10, h = (n >> 5) & 31, w = n & 31;
        float sz = xla_logistic(pred_boxes[(b * 3 + 0) * NPTS + n]);
        float sy = xla_logistic(pred_boxes[(b * 3 + 1) * NPTS + n]);
        float sx = xla_logistic(pred_boxes[(b * 3 + 2) * NPTS + n]);
        float pz = __fmul_rn(__fdiv_rn(__fadd_rn((float)d, sz),  4.0f),  3.0f);
        float py = __fmul_rn(__fdiv_rn(__fadd_rn((float)h, sy), 32.0f), 25.0f);
        float px = __fmul_rn(__fdiv_rn(__fadd_rn((float)w, sx), 32.0f), 25.0f);
        float aa = __fadd_rn(__fadd_rn(__fmul_rn(pz, pz), __fmul_rn(py, py)),
                             __fmul_rn(px, px));
        unsigned cb  = __float_as_uint(conf);
        unsigned ord = cb ^ ((cb & 0x80000000u) ? 0xFFFFFFFFu : 0x80000000u);
        g_pos[prob][n]  = make_float4(pz, py, px, aa);
        g_prio[prob][n] = ~ord;
    }
}

// ---------------------------------------------------------------------------
// K2: conflict edges via 40-offset half stencil, positions staged in shared.
// grid (16, NPROB) x 256.
// ---------------------------------------------------------------------------
__global__ __launch_bounds__(256) void k_edges()
{
    extern __shared__ __align__(16) unsigned char dyn2[];
    float4* s_pos = (float4*)dyn2;                 // 64 KB
    __shared__ unsigned s_vm[NW];
    __shared__ unsigned s_eb[BEC];
    __shared__ int s_ne, s_nt, s_base, s_tab[40];

    int prob = blockIdx.y;
    float c2 = (prob & 1) ? 0.5625f : 1.0f;
    int tid  = threadIdx.x;

    if (tid == 0) { s_ne = 0; s_nt = 0; }
    for (int w = tid; w < NW; w += 256) s_vm[w] = g_vmask[prob][w];
    build_stencil(tid, 1, s_tab, &s_nt);
    for (int i = tid; i < NPTS; i += 256) s_pos[i] = g_pos[prob][i];
    __syncthreads();

    int n = blockIdx.x * 256 + tid;
    if ((s_vm[n >> 5] >> (n & 31)) & 1) {
        float4 pj = s_pos[n];
        unsigned poj = g_prio[prob][n];
        int d = n >> 10, h = (n >> 5) & 31, w0 = n & 31;

        #pragma unroll 4
        for (int k = 0; k < 40; k++) {
            int v  = s_tab[k];
            int d2 = d  + (v & 7) - 2;
            int h2 = h  + ((v >> 3) & 7) - 2;
            int w2 = w0 + ((v >> 6) & 7) - 2;
            if ((unsigned)d2 > 3u || (unsigned)h2 > 31u || (unsigned)w2 > 31u)
                continue;
            int n2 = (d2 << 10) | (h2 << 5) | w2;
            if (!((s_vm[n2 >> 5] >> (n2 & 31)) & 1)) continue;
            float4 pi = s_pos[n2];
            float dot = __fadd_rn(__fadd_rn(__fmul_rn(pi.x, pj.x),
                                            __fmul_rn(pi.y, pj.y)),
                                  __fmul_rn(pi.z, pj.z));
            float dist = __fsub_rn(__fadd_rn(pi.w, pj.w), __fmul_rn(2.0f, dot));
            if (dist < c2) {
                unsigned poi = g_prio[prob][n2];
                unsigned pred, succ;
                if (poi < poj || (poi == poj && n2 < n)) { pred = (unsigned)n2; succ = (unsigned)n; }
                else                                     { pred = (unsigned)n;  succ = (unsigned)n2; }
                unsigned pk = (succ << 12) | pred;
                int e = atomicAdd(&s_ne, 1);
                if (e < BEC) s_eb[e] = pk;
                else {
                    int ge = atomicAdd(&g_ecnt[prob], 1);
                    if (ge < EMAXG) g_edges[prob][ge] = pk;
                }
            }
        }
    }
    __syncthreads();
    int ne = s_ne < BEC ? s_ne : BEC;
    if (tid == 0) s_base = atomicAdd(&g_ecnt[prob], ne);
    __syncthreads();
    for (int e = tid; e < ne; e += 256) {
        int ge = s_base + e;
        if (ge < EMAXG) g_edges[prob][ge] = s_eb[e];
    }
}

// ---------------------------------------------------------------------------
// K3: NMS fixed-point iterations on sparse edges (staged in shared).
// grid NPROB x 1024.  Writes alive bitset + lp.
// ---------------------------------------------------------------------------
__global__ __launch_bounds__(1024, 1) void k_nms()
{
    extern __shared__ unsigned dsm[];
    unsigned* alive = dsm;
    unsigned* Fb    = dsm + NW;
    unsigned* bF    = dsm + 2 * NW;
    unsigned* bA    = dsm + 3 * NW;
    unsigned* s_ed  = dsm + 4 * NW;
    __shared__ int s_ch, s_lp;

    int prob = blockIdx.x;
    int tid  = threadIdx.x;
    int E    = g_ecnt[prob]; if (E > EMAXG) E = EMAXG;
    int Es   = E < SEC ? E : SEC;

    for (int e = tid; e < Es; e += 1024) s_ed[e] = g_edges[prob][e];
    if (tid < NW) alive[tid] = g_vmask[prob][tid];
    if (tid == 0) s_lp = 0;
    __syncthreads();

    for (int it = 0; it < 32; it++) {
        if (tid < NW) bF[tid] = 0;
        if (tid == 0) s_ch = 0;
        __syncthreads();
        for (int e = tid; e < Es; e += 1024) {
            unsigned pk = s_ed[e];
            int p = pk & 0xFFF, s = pk >> 12;
            if ((alive[p >> 5] >> (p & 31)) & 1)
                atomicOr(&bF[s >> 5], 1u << (s & 31));
        }
        for (int e = Es + tid; e < E; e += 1024) {
            unsigned pk = g_edges[prob][e];
            int p = pk & 0xFFF, s = pk >> 12;
            if ((alive[p >> 5] >> (p & 31)) & 1)
                atomicOr(&bF[s >> 5], 1u << (s & 31));
        }
        __syncthreads();
        if (tid < NW) { Fb[tid] = alive[tid] & ~bF[tid]; bA[tid] = 0; }
        __syncthreads();
        for (int e = tid; e < Es; e += 1024) {
            unsigned pk = s_ed[e];
            int p = pk & 0xFFF, s = pk >> 12;
            if ((Fb[p >> 5] >> (p & 31)) & 1)
                atomicOr(&bA[s >> 5], 1u << (s & 31));
        }
        for (int e = Es + tid; e < E; e += 1024) {
            unsigned pk = g_edges[prob][e];
            int p = pk & 0xFFF, s = pk >> 12;
            if ((Fb[p >> 5] >> (p & 31)) & 1)
                atomicOr(&bA[s >> 5], 1u << (s & 31));
        }
        __syncthreads();
        if (tid < NW) {
            unsigned na = alive[tid] & ~bA[tid];
            if (na != alive[tid]) s_ch = 1;
            alive[tid] = na;
        }
        __syncthreads();
        int stop = (s_ch == 0);   // fixed point => all later iters identical
        __syncthreads();
        if (stop) break;
    }

    // lp = popcount(alive): pz in [0,3.0] always, 3.0 < 3+1e-5 -> filter vacuous
    if (tid < NW) {
        int c = __popc(alive[tid]);
        c = __reduce_add_sync(0xFFFFFFFFu, c);
        if ((tid & 31) == 0 && c) atomicAdd(&s_lp, c);
        g_alive[prob][tid] = alive[tid];
    }
    __syncthreads();
    if (tid == 0) g_cnt[prob][1] = s_lp;
}

// ---------------------------------------------------------------------------
// K4: target matching via 81-offset full stencil (incl. center), positions
// staged in shared.  grid (16, NPROB) x 256 — one thread per cell.
// ---------------------------------------------------------------------------
__global__ __launch_bounds__(256) void k_match(
    const int*   __restrict__ targ_clses,
    const float* __restrict__ targ_boxes)
{
    extern __shared__ __align__(16) unsigned char dyn4[];
    float4* s_pos = (float4*)dyn4;                 // 64 KB
    __shared__ unsigned s_al[NW];
    __shared__ int s_nt, s_tab[81], sLT, sTP;

    int prob = blockIdx.y;
    int b    = prob >> 1;
    int cls  = (prob & 1) + 1;
    float c2 = (prob & 1) ? 0.5625f : 1.0f;
    const float HI = (float)(3.0 + 1e-05);
    int tid  = threadIdx.x;

    if (tid == 0) { s_nt = 0; sLT = 0; sTP = 0; }
    for (int w = tid; w < NW; w += 256) s_al[w] = g_alive[prob][w];
    build_stencil(tid, 0, s_tab, &s_nt);
    for (int i = tid; i < NPTS; i += 256) s_pos[i] = g_pos[prob][i];
    __syncthreads();
    int nt = s_nt;   // 81

    int n = blockIdx.x * 256 + tid;
    int lt = 0, tp = 0;
    if (targ_clses[b * NPTS + n] == cls) {
        int d = n >> 10, h = (n >> 5) & 31, w0 = n & 31;
        float t0 = targ_boxes[(b * NPTS + n) * 3 + 0];
        float t1 = targ_boxes[(b * NPTS + n) * 3 + 1];
        float t2 = targ_boxes[(b * NPTS + n) * 3 + 2];
        float tz = __fmul_rn(__fdiv_rn(__fadd_rn((float)d, t0),  4.0f),  3.0f);
        float ty = __fmul_rn(__fdiv_rn(__fadd_rn((float)h, t1), 32.0f), 25.0f);
        float tx = __fmul_rn(__fdiv_rn(__fadd_rn((float)w0, t2), 32.0f), 25.0f);
        if (tz >= 0.0f && tz < HI) {
            lt = 1;
            float bbt = __fadd_rn(__fadd_rn(__fmul_rn(tz, tz), __fmul_rn(ty, ty)),
                                  __fmul_rn(tx, tx));
            bool found = false;
            for (int k = 0; k < nt && !found; k++) {
                int v  = s_tab[k];
                int d2 = d  + (v & 7) - 2;
                int h2 = h  + ((v >> 3) & 7) - 2;
                int w2 = w0 + ((v >> 6) & 7) - 2;
                if ((unsigned)d2 > 3u || (unsigned)h2 > 31u || (unsigned)w2 > 31u)
                    continue;
                int n2 = (d2 << 10) | (h2 << 5) | w2;
                if (!((s_al[n2 >> 5] >> (n2 & 31)) & 1)) continue;
                float4 p = s_pos[n2];
                float dot = __fadd_rn(__fadd_rn(__fmul_rn(p.x, tz),
                                                __fmul_rn(p.y, ty)),
                                      __fmul_rn(p.z, tx));
                float dist = __fsub_rn(__fadd_rn(p.w, bbt), __fmul_rn(2.0f, dot));
                if (dist < c2) found = true;
            }
            if (found) tp = 1;
        }
    }
    lt = __reduce_add_sync(0xFFFFFFFFu, lt);
    tp = __reduce_add_sync(0xFFFFFFFFu, tp);
    if ((tid & 31) == 0) {
        if (lt) atomicAdd(&sLT, lt);
        if (tp) atomicAdd(&sTP, tp);
    }
    __syncthreads();
    if (tid == 0) {
        if (sLT) atomicAdd(&g_cnt[prob][2], sLT);
        if (sTP) atomicAdd(&g_cnt[prob][0], sTP);
    }
}

// ---------------------------------------------------------------------------
// K5: finalize — out[prob*3 + {0,1,2}] = {tp, fp, fn} as float32
// ---------------------------------------------------------------------------
__global__ void k_final(float* __restrict__ out)
{
    int p = threadIdx.x;
    if (p < NPROB) {
        int tp = g_cnt[p][0], lp = g_cnt[p][1], lt = g_cnt[p][2];
        out[p * 3 + 0] = (float)tp;
        out[p * 3 + 1] = (float)(lp - tp);
        out[p * 3 + 2] = (float)(lt - tp);
    }
}

extern "C" void kernel_launch(void* const* d_in, const int* in_sizes, int n_in,
                              void* d_out, int out_size)
{
    const float* pred_clses = (const float*)d_in[0];
    const float* pred_boxes = (const float*)d_in[1];
    const int*   targ_clses = (const int*)d_in[2];
    const float* targ_boxes = (const float*)d_in[3];
    float* out = (float*)d_out;

    static int smem_set = 0;
    int k3_smem = (4 * NW + SEC) * sizeof(unsigned);
    if (!smem_set) {
        cudaFuncSetAttribute(k_nms,   cudaFuncAttributeMaxDynamicSharedMemorySize, k3_smem);
        cudaFuncSetAttribute(k_edges, cudaFuncAttributeMaxDynamicSharedMemorySize, POSB);
        cudaFuncSetAttribute(k_match, cudaFuncAttributeMaxDynamicSharedMemorySize, POSB);
        smem_set = 1;
    }

    k_prep <<<dim3(16, NPROB), 256>>>(pred_clses, pred_boxes);
    k_edges<<<dim3(16, NPROB), 256, POSB>>>();
    k_nms  <<<NPROB, 1024, k3_smem>>>();
    k_match<<<dim3(16, NPROB), 256, POSB>>>(targ_clses, targ_boxes);
    k_final<<<1, 32>>>(out);
}

// round 17
// speedup vs baseline: 1.7980x; 1.7980x over previous
#include <cuda_runtime.h>

#define NPTS   4096
#define NPROB  4
#define NW     128             // 4096 cells / 32
#define EMAXG  (1 << 17)       // global edge capacity per problem
#define SEC    16384           // K3 shared edge stage capacity

static __device__ float4   g_pos[NPROB][NPTS];    // .x=z .y=y .z=x .w=aa
static __device__ unsigned g_prio[NPROB][NPTS];   // priority bits (asc = higher)
static __device__ unsigned g_vmask[NPROB][NW];    // valid-cell bitset
static __device__ unsigned g_alive[NPROB][NW];    // post-NMS alive bitset
static __device__ unsigned g_edges[NPROB][EMAXG]; // (succ<<12)|pred (cell ids)
static __device__ int      g_ecnt[NPROB];
static __device__ int      g_cnt[NPROB][3];       // tp, lp, lt

// XLA logistic(x) = 0.5 + 0.5*tanh(0.5x), Eigen rational tanh (bit-matched)
__device__ __forceinline__ float xla_logistic(float x) {
    float t  = 0.5f * x;
    float ax = fabsf(t);
    float xc = fminf(fmaxf(t, -7.90531110763549805f), 7.90531110763549805f);
    float x2 = xc * xc;
    float p = fmaf(x2, -2.76076847742355e-16f, 2.00018790482477e-13f);
    p = fmaf(x2, p, -8.60467152213735e-11f);
    p = fmaf(x2, p,  5.12229709037114e-08f);
    p = fmaf(x2, p,  1.48572235717979e-05f);
    p = fmaf(x2, p,  6.37261928875436e-04f);
    p = fmaf(x2, p,  4.89352455891786e-03f);
    p = xc * p;
    float q = fmaf(x2, 1.19825839466702e-06f, 1.18534705686654e-04f);
    q = fmaf(x2, q, 2.26843463243900e-03f);
    q = fmaf(x2, q, 4.89352518554385e-03f);
    float y = p / q;
    if (ax < 0.0004f) y = t;
    return __fadd_rn(__fmul_rn(0.5f, y), 0.5f);
}

// 5x5x5 stencil minus offsets with >=2 coords of |2| (min dist^2 there
// > 1.125 > cutoff^2, margin >> fp rounding).  half=1: lexicographically-
// positive offsets only (40; center excluded by lex).  half=0: full incl.
// center (81).  CALLER MUST __syncthreads() AFTER zeroing *cnt and BEFORE
// calling this (atomicAdd races with the init otherwise — R16 bug).
__device__ __forceinline__ void build_stencil(int tid, int half,
                                              int* tab, int* cnt)
{
    if (tid < 125) {
        int dz = tid / 25 - 2;
        int r  = tid % 25;
        int dy = r / 5 - 2;
        int dx = r % 5 - 2;
        int n2c = (dz == 2 || dz == -2) + (dy == 2 || dy == -2) +
                  (dx == 2 || dx == -2);
        bool keep = (n2c < 2);
        if (half)
            keep = keep && ((dz > 0) || (dz == 0 && (dy > 0 || (dy == 0 && dx > 0))));
        if (keep) {
            int s = atomicAdd(cnt, 1);
            tab[s] = (dz + 2) | ((dy + 2) << 3) | ((dx + 2) << 6);
        }
    }
}

// ---------------------------------------------------------------------------
// K1: per-cell conf/argmax, positions (+aa), priority, validity bitset.
// grid (16, NPROB) x 256 — one thread per cell.
// ---------------------------------------------------------------------------
__global__ __launch_bounds__(256) void k_prep(
    const float* __restrict__ pred_clses,
    const float* __restrict__ pred_boxes)
{
    int prob = blockIdx.y;
    int b    = prob >> 1;
    int cls  = (prob & 1) + 1;
    int tid  = threadIdx.x;
    int n    = blockIdx.x * 256 + tid;

    if (blockIdx.x == 0) {
        if (tid == 0) g_ecnt[prob] = 0;
        if (tid < 3)  g_cnt[prob][tid] = 0;
    }

    float cv0 = pred_clses[(b * 3 + 0) * NPTS + n];
    float cv1 = pred_clses[(b * 3 + 1) * NPTS + n];
    float cv2 = pred_clses[(b * 3 + 2) * NPTS + n];
    float conf = cv0; int arg = 0;
    if (cv1 > conf) { conf = cv1; arg = 1; }
    if (cv2 > conf) { conf = cv2; arg = 2; }
    bool valid = (arg == cls);

    unsigned bal = __ballot_sync(0xFFFFFFFFu, valid);
    if ((tid & 31) == 0) g_vmask[prob][n >> 5] = bal;

    if (valid) {
        int d = n >> 10, h = (n >> 5) & 31, w = n & 31;
        float sz = xla_logistic(pred_boxes[(b * 3 + 0) * NPTS + n]);
        float sy = xla_logistic(pred_boxes[(b * 3 + 1) * NPTS + n]);
        float sx = xla_logistic(pred_boxes[(b * 3 + 2) * NPTS + n]);
        float pz = __fmul_rn(__fdiv_rn(__fadd_rn((float)d, sz),  4.0f),  3.0f);
        float py = __fmul_rn(__fdiv_rn(__fadd_rn((float)h, sy), 32.0f), 25.0f);
        float px = __fmul_rn(__fdiv_rn(__fadd_rn((float)w, sx), 32.0f), 25.0f);
        float aa = __fadd_rn(__fadd_rn(__fmul_rn(pz, pz), __fmul_rn(py, py)),
                             __fmul_rn(px, px));
        unsigned cb  = __float_as_uint(conf);
        unsigned ord = cb ^ ((cb & 0x80000000u) ? 0xFFFFFFFFu : 0x80000000u);
        g_pos[prob][n]  = make_float4(pz, py, px, aa);
        g_prio[prob][n] = ~ord;
    }
}

// ---------------------------------------------------------------------------
// K2: conflict edges — WARP per cell, lanes over the 40-offset half stencil
// (2 parallel rounds).  Direct global atomic emit (hits rare).
// grid (256, NPROB) x 512 — 16 warps/block, cell = blockIdx.x*16 + warp.
// ---------------------------------------------------------------------------
__global__ __launch_bounds__(512) void k_edges()
{
    __shared__ unsigned s_vm[NW];
    __shared__ int s_nt, s_tab[40];

    int prob = blockIdx.y;
    float c2 = (prob & 1) ? 0.5625f : 1.0f;
    int tid  = threadIdx.x;
    int warp = tid >> 5, lane = tid & 31;

    if (tid == 0) s_nt = 0;
    for (int w = tid; w < NW; w += 512) s_vm[w] = g_vmask[prob][w];
    __syncthreads();                     // s_nt init visible before atomicAdd
    build_stencil(tid, 1, s_tab, &s_nt);
    __syncthreads();

    int n = blockIdx.x * 16 + warp;
    if (!((s_vm[n >> 5] >> (n & 31)) & 1)) return;   // warp-uniform

    float4 pj = g_pos[prob][n];          // broadcast load
    unsigned poj = g_prio[prob][n];
    int d = n >> 10, h = (n >> 5) & 31, w0 = n & 31;

    for (int k = lane; k < 40; k += 32) {
        int v  = s_tab[k];
        int d2 = d  + (v & 7) - 2;
        int h2 = h  + ((v >> 3) & 7) - 2;
        int w2 = w0 + ((v >> 6) & 7) - 2;
        if ((unsigned)d2 > 3u || (unsigned)h2 > 31u || (unsigned)w2 > 31u)
            continue;
        int n2 = (d2 << 10) | (h2 << 5) | w2;
        if (!((s_vm[n2 >> 5] >> (n2 & 31)) & 1)) continue;
        float4 pi = g_pos[prob][n2];
        float dot = __fadd_rn(__fadd_rn(__fmul_rn(pi.x, pj.x),
                                        __fmul_rn(pi.y, pj.y)),
                              __fmul_rn(pi.z, pj.z));
        float dist = __fsub_rn(__fadd_rn(pi.w, pj.w), __fmul_rn(2.0f, dot));
        if (dist < c2) {
            unsigned poi = g_prio[prob][n2];
            unsigned pred, succ;
            if (poi < poj || (poi == poj && n2 < n)) { pred = (unsigned)n2; succ = (unsigned)n; }
            else                                     { pred = (unsigned)n;  succ = (unsigned)n2; }
            int ge = atomicAdd(&g_ecnt[prob], 1);
            if (ge < EMAXG) g_edges[prob][ge] = (succ << 12) | pred;
        }
    }
}

// ---------------------------------------------------------------------------
// K3: NMS fixed-point iterations on sparse edges (staged in shared).
// grid NPROB x 1024.  Writes alive bitset + lp.
// ---------------------------------------------------------------------------
__global__ __launch_bounds__(1024, 1) void k_nms()
{
    extern __shared__ unsigned dsm[];
    unsigned* alive = dsm;
    unsigned* Fb    = dsm + NW;
    unsigned* bF    = dsm + 2 * NW;
    unsigned* bA    = dsm + 3 * NW;
    unsigned* s_ed  = dsm + 4 * NW;
    __shared__ int s_ch, s_lp;

    int prob = blockIdx.x;
    int tid  = threadIdx.x;
    int E    = g_ecnt[prob]; if (E > EMAXG) E = EMAXG;
    int Es   = E < SEC ? E : SEC;

    for (int e = tid; e < Es; e += 1024) s_ed[e] = g_edges[prob][e];
    if (tid < NW) alive[tid] = g_vmask[prob][tid];
    if (tid == 0) s_lp = 0;
    __syncthreads();

    for (int it = 0; it < 32; it++) {
        if (tid < NW) bF[tid] = 0;
        if (tid == 0) s_ch = 0;
        __syncthreads();
        for (int e = tid; e < Es; e += 1024) {
            unsigned pk = s_ed[e];
            int p = pk & 0xFFF, s = pk >> 12;
            if ((alive[p >> 5] >> (p & 31)) & 1)
                atomicOr(&bF[s >> 5], 1u << (s & 31));
        }
        for (int e = Es + tid; e < E; e += 1024) {
            unsigned pk = g_edges[prob][e];
            int p = pk & 0xFFF, s = pk >> 12;
            if ((alive[p >> 5] >> (p & 31)) & 1)
                atomicOr(&bF[s >> 5], 1u << (s & 31));
        }
        __syncthreads();
        if (tid < NW) { Fb[tid] = alive[tid] & ~bF[tid]; bA[tid] = 0; }
        __syncthreads();
        for (int e = tid; e < Es; e += 1024) {
            unsigned pk = s_ed[e];
            int p = pk & 0xFFF, s = pk >> 12;
            if ((Fb[p >> 5] >> (p & 31)) & 1)
                atomicOr(&bA[s >> 5], 1u << (s & 31));
        }
        for (int e = Es + tid; e < E; e += 1024) {
            unsigned pk = g_edges[prob][e];
            int p = pk & 0xFFF, s = pk >> 12;
            if ((Fb[p >> 5] >> (p & 31)) & 1)
                atomicOr(&bA[s >> 5], 1u << (s & 31));
        }
        __syncthreads();
        if (tid < NW) {
            unsigned na = alive[tid] & ~bA[tid];
            if (na != alive[tid]) s_ch = 1;
            alive[tid] = na;
        }
        __syncthreads();
        int stop = (s_ch == 0);   // fixed point => all later iters identical
        __syncthreads();
        if (stop) break;
    }

    // lp = popcount(alive): pz in [0,3.0] always, 3.0 < 3+1e-5 -> filter vacuous
    if (tid < NW) {
        int c = __popc(alive[tid]);
        c = __reduce_add_sync(0xFFFFFFFFu, c);
        if ((tid & 31) == 0 && c) atomicAdd(&s_lp, c);
        g_alive[prob][tid] = alive[tid];
    }
    __syncthreads();
    if (tid == 0) g_cnt[prob][1] = s_lp;
}

// ---------------------------------------------------------------------------
// K4: target matching — WARP per target cell, lanes over the 81-offset full
// stencil (3 parallel rounds), ballot reduce.
// grid (256, NPROB) x 512 — cell = blockIdx.x*16 + warp.
// ---------------------------------------------------------------------------
__global__ __launch_bounds__(512) void k_match(
    const int*   __restrict__ targ_clses,
    const float* __restrict__ targ_boxes)
{
    __shared__ unsigned s_al[NW];
    __shared__ int s_nt, s_tab[81], sLT, sTP;

    int prob = blockIdx.y;
    int b    = prob >> 1;
    int cls  = (prob & 1) + 1;
    float c2 = (prob & 1) ? 0.5625f : 1.0f;
    const float HI = (float)(3.0 + 1e-05);
    int tid  = threadIdx.x;
    int warp = tid >> 5, lane = tid & 31;

    if (tid == 0) { s_nt = 0; sLT = 0; sTP = 0; }
    for (int w = tid; w < NW; w += 512) s_al[w] = g_alive[prob][w];
    __syncthreads();                     // s_nt init visible before atomicAdd
    build_stencil(tid, 0, s_tab, &s_nt);
    __syncthreads();
    int nt = s_nt;   // 81

    int n = blockIdx.x * 16 + warp;
    int lt = 0, tp = 0;
    if (targ_clses[b * NPTS + n] == cls) {       // warp-uniform broadcast
        int d = n >> 10, h = (n >> 5) & 31, w0 = n & 31;
        float t0 = targ_boxes[(b * NPTS + n) * 3 + 0];
        float t1 = targ_boxes[(b * NPTS + n) * 3 + 1];
        float t2 = targ_boxes[(b * NPTS + n) * 3 + 2];
        float tz = __fmul_rn(__fdiv_rn(__fadd_rn((float)d, t0),  4.0f),  3.0f);
        float ty = __fmul_rn(__fdiv_rn(__fadd_rn((float)h, t1), 32.0f), 25.0f);
        float tx = __fmul_rn(__fdiv_rn(__fadd_rn((float)w0, t2), 32.0f), 25.0f);
        if (tz >= 0.0f && tz < HI) {             // uniform (same data all lanes)
            lt = 1;
            float bbt = __fadd_rn(__fadd_rn(__fmul_rn(tz, tz), __fmul_rn(ty, ty)),
                                  __fmul_rn(tx, tx));
            bool hit = false;
            for (int k = lane; k < nt; k += 32) {
                int v  = s_tab[k];
                int d2 = d  + (v & 7) - 2;
                int h2 = h  + ((v >> 3) & 7) - 2;
                int w2 = w0 + ((v >> 6) & 7) - 2;
                if ((unsigned)d2 > 3u || (unsigned)h2 > 31u || (unsigned)w2 > 31u)
                    continue;
                int n2 = (d2 << 10) | (h2 << 5) | w2;
                if (!((s_al[n2 >> 5] >> (n2 & 31)) & 1)) continue;
                float4 p = g_pos[prob][n2];
                float dot = __fadd_rn(__fadd_rn(__fmul_rn(p.x, tz),
                                                __fmul_rn(p.y, ty)),
                                      __fmul_rn(p.z, tx));
                float dist = __fsub_rn(__fadd_rn(p.w, bbt), __fmul_rn(2.0f, dot));
                hit |= (dist < c2);
            }
            tp = (__ballot_sync(0xFFFFFFFFu, hit) != 0) ? 1 : 0;
        }
    }
    if (lane == 0) {
        if (lt) atomicAdd(&sLT, 1);
        if (tp) atomicAdd(&sTP, 1);
    }
    __syncthreads();
    if (tid == 0) {
        if (sLT) atomicAdd(&g_cnt[prob][2], sLT);
        if (sTP) atomicAdd(&g_cnt[prob][0], sTP);
    }
}

// ---------------------------------------------------------------------------
// K5: finalize — out[prob*3 + {0,1,2}] = {tp, fp, fn} as float32
// ---------------------------------------------------------------------------
__global__ void k_final(float* __restrict__ out)
{
    int p = threadIdx.x;
    if (p < NPROB) {
        int tp = g_cnt[p][0], lp = g_cnt[p][1], lt = g_cnt[p][2];
        out[p * 3 + 0] = (float)tp;
        out[p * 3 + 1] = (float)(lp - tp);
        out[p * 3 + 2] = (float)(lt - tp);
    }
}

extern "C" void kernel_launch(void* const* d_in, const int* in_sizes, int n_in,
                              void* d_out, int out_size)
{
    const float* pred_clses = (const float*)d_in[0];
    const float* pred_boxes = (const float*)d_in[1];
    const int*   targ_clses = (const int*)d_in[2];
    const float* targ_boxes = (const float*)d_in[3];
    float* out = (float*)d_out;

    static int smem_set = 0;
    int k3_smem = (4 * NW + SEC) * sizeof(unsigned);
    if (!smem_set) {
        cudaFuncSetAttribute(k_nms, cudaFuncAttributeMaxDynamicSharedMemorySize,
                             k3_smem);
        smem_set = 1;
    }

    k_prep <<<dim3(16, NPROB),  256>>>(pred_clses, pred_boxes);
    k_edges<<<dim3(256, NPROB), 512>>>();
    k_nms  <<<NPROB, 1024, k3_smem>>>();
    k_match<<<dim3(256, NPROB), 512>>>(targ_clses, targ_boxes);
    k_final<<<1, 32>>>(out);
}